// round 1
// baseline (speedup 1.0000x reference)
#include <cuda_runtime.h>

#define NN 100000
#define FF 128
#define DD 32

// Scratch (device globals: allocation-free rule)
__device__ __align__(128) float g_t [NN * DD];   // t = act(h) @ Wn (messages)
__device__ __align__(128) float g_a1[NN * DD];   // layer outputs, PRE-relu
__device__ __align__(128) float g_a2[NN * DD];
__device__ __align__(128) float g_a3[NN * DD];

// ---------------------------------------------------------------------------
// Fused transform: for a tile of NODES nodes,
//   t[n]   = act(h[n]) @ Wn
//   agg[n] = act(h[n]) @ Ws + bn        (self term pre-seeds the aggregation)
// 8 threads per node; each thread owns one float4 of the 32-wide output.
// ---------------------------------------------------------------------------
template<int DIN, int NODES, bool RELU_IN>
__global__ __launch_bounds__(NODES * 8)
void transform_kernel(const float* __restrict__ hin,
                      const float* __restrict__ Wn,
                      const float* __restrict__ Ws,
                      const float* __restrict__ bn,
                      float* __restrict__ t,
                      float* __restrict__ agg)
{
    constexpr int THREADS = NODES * 8;
    __shared__ float xs[NODES][DIN + 1];     // +1 pad: conflict-free column reads
    __shared__ float wn_s[DIN][32];
    __shared__ float ws_s[DIN][32];

    const int tid   = threadIdx.x;
    const int node0 = blockIdx.x * NODES;

    // Stage weights (broadcast across blocks -> L2 hits)
    for (int i = tid; i < DIN * 32; i += THREADS) {
        ((float*)wn_s)[i] = Wn[i];
        ((float*)ws_s)[i] = Ws[i];
    }
    // Stage node features, coalesced, with optional input ReLU
    for (int i = tid; i < NODES * DIN; i += THREADS) {
        int r = i / DIN, c = i % DIN;
        float v = hin[(node0 + r) * DIN + c];
        if (RELU_IN) v = fmaxf(v, 0.0f);
        xs[r][c] = v;
    }
    __syncthreads();

    const int ln = tid >> 3;          // local node
    const int g4 = (tid & 7) * 4;     // output float4 offset

    float4 an = make_float4(0.f, 0.f, 0.f, 0.f);
    float4 as = *(const float4*)(bn + g4);   // seed with bias

    #pragma unroll
    for (int k = 0; k < DIN; ++k) {
        const float  xv  = xs[ln][k];
        const float4 wn4 = *(const float4*)&wn_s[k][g4];
        const float4 ws4 = *(const float4*)&ws_s[k][g4];
        an.x = fmaf(xv, wn4.x, an.x);
        an.y = fmaf(xv, wn4.y, an.y);
        an.z = fmaf(xv, wn4.z, an.z);
        an.w = fmaf(xv, wn4.w, an.w);
        as.x = fmaf(xv, ws4.x, as.x);
        as.y = fmaf(xv, ws4.y, as.y);
        as.z = fmaf(xv, ws4.z, as.z);
        as.w = fmaf(xv, ws4.w, as.w);
    }

    const int node = node0 + ln;
    *(float4*)(t   + node * 32 + g4) = an;
    *(float4*)(agg + node * 32 + g4) = as;
}

// ---------------------------------------------------------------------------
// Edge scatter: agg[dst] += t[src]. 8 lanes per edge, one float4 each.
// Each edge = exactly one coalesced 128B gather + one 128B vector RED.
// ---------------------------------------------------------------------------
__global__ __launch_bounds__(256)
void scatter_kernel(const int* __restrict__ src, const int* __restrict__ dst,
                    const float* __restrict__ t, float* __restrict__ agg, int E)
{
    const int g = blockIdx.x * blockDim.x + threadIdx.x;   // < 25.6M, fits int
    const int e = g >> 3;
    if (e >= E) return;
    const int c4 = (g & 7) * 4;
    const int s = src[e];
    const int d = dst[e];
    const float4 v = *(const float4*)(t + s * 32 + c4);
    float* p = agg + d * 32 + c4;
    asm volatile("red.global.add.v4.f32 [%0], {%1,%2,%3,%4};"
                 :: "l"(p), "f"(v.x), "f"(v.y), "f"(v.z), "f"(v.w)
                 : "memory");
}

// ---------------------------------------------------------------------------
// Final FC + log_softmax over concat([x, relu(a1), relu(a2), relu(a3)])
// One thread per node; fc weights staged in shared (broadcast reads).
// ---------------------------------------------------------------------------
__global__ __launch_bounds__(256)
void fc_kernel(const float* __restrict__ x,
               const float* __restrict__ a1, const float* __restrict__ a2,
               const float* __restrict__ a3,
               const float* __restrict__ fcw, const float* __restrict__ fcb,
               float* __restrict__ out, int N)
{
    __shared__ float w_s[(FF + 3 * DD) * 10];   // 2240 floats
    for (int i = threadIdx.x; i < (FF + 3 * DD) * 10; i += blockDim.x)
        w_s[i] = fcw[i];
    __syncthreads();

    const int node = blockIdx.x * blockDim.x + threadIdx.x;
    if (node >= N) return;

    float acc[10];
    #pragma unroll
    for (int c = 0; c < 10; ++c) acc[c] = fcb[c];

    int k = 0;
    // x segment (no relu)
    {
        const float4* r = (const float4*)(x + node * FF);
        for (int q = 0; q < FF / 4; ++q) {
            float4 f4 = r[q];
            float fv[4] = {f4.x, f4.y, f4.z, f4.w};
            #pragma unroll
            for (int j = 0; j < 4; ++j) {
                const float f = fv[j];
                #pragma unroll
                for (int c = 0; c < 10; ++c)
                    acc[c] = fmaf(f, w_s[k * 10 + c], acc[c]);
                ++k;
            }
        }
    }
    // hidden segments (relu at read)
    const float* const hs[3] = {a1, a2, a3};
    for (int l = 0; l < 3; ++l) {
        const float4* r = (const float4*)(hs[l] + node * DD);
        for (int q = 0; q < DD / 4; ++q) {
            float4 f4 = r[q];
            float fv[4] = {f4.x, f4.y, f4.z, f4.w};
            #pragma unroll
            for (int j = 0; j < 4; ++j) {
                const float f = fmaxf(fv[j], 0.0f);
                #pragma unroll
                for (int c = 0; c < 10; ++c)
                    acc[c] = fmaf(f, w_s[k * 10 + c], acc[c]);
                ++k;
            }
        }
    }

    // log_softmax
    float m = acc[0];
    #pragma unroll
    for (int c = 1; c < 10; ++c) m = fmaxf(m, acc[c]);
    float s = 0.f;
    #pragma unroll
    for (int c = 0; c < 10; ++c) s += expf(acc[c] - m);
    const float lse = m + logf(s);
    #pragma unroll
    for (int c = 0; c < 10; ++c) out[node * 10 + c] = acc[c] - lse;
}

// ---------------------------------------------------------------------------
extern "C" void kernel_launch(void* const* d_in, const int* in_sizes, int n_in,
                              void* d_out, int out_size)
{
    const float* x   = (const float*)d_in[0];
    const int*   src = (const int*)  d_in[1];
    const int*   dst = (const int*)  d_in[2];
    const float* Wn0 = (const float*)d_in[3];
    const float* bn0 = (const float*)d_in[4];
    const float* Ws0 = (const float*)d_in[5];
    const float* Wn1 = (const float*)d_in[6];
    const float* bn1 = (const float*)d_in[7];
    const float* Ws1 = (const float*)d_in[8];
    const float* Wn2 = (const float*)d_in[9];
    const float* bn2 = (const float*)d_in[10];
    const float* Ws2 = (const float*)d_in[11];
    const float* fcw = (const float*)d_in[12];
    const float* fcb = (const float*)d_in[13];
    float* out = (float*)d_out;

    const int N = in_sizes[0] / FF;
    const int E = in_sizes[1];

    float *t, *a1, *a2, *a3;
    cudaGetSymbolAddress((void**)&t,  g_t);
    cudaGetSymbolAddress((void**)&a1, g_a1);
    cudaGetSymbolAddress((void**)&a2, g_a2);
    cudaGetSymbolAddress((void**)&a3, g_a3);

    const int scatter_blocks = (E * 8 + 255) / 256;

    // Layer 0 (din = 128, input is raw x)
    transform_kernel<FF, 16, false><<<N / 16, 128>>>(x, Wn0, Ws0, bn0, t, a1);
    scatter_kernel<<<scatter_blocks, 256>>>(src, dst, t, a1, E);

    // Layer 1 (din = 32, relu on read of pre-activation a1)
    transform_kernel<DD, 32, true><<<N / 32, 256>>>(a1, Wn1, Ws1, bn1, t, a2);
    scatter_kernel<<<scatter_blocks, 256>>>(src, dst, t, a2, E);

    // Layer 2
    transform_kernel<DD, 32, true><<<N / 32, 256>>>(a2, Wn2, Ws2, bn2, t, a3);
    scatter_kernel<<<scatter_blocks, 256>>>(src, dst, t, a3, E);

    // FC + log_softmax
    fc_kernel<<<(N + 255) / 256, 256>>>(x, a1, a2, a3, fcw, fcb, out, N);
}

// round 2
// speedup vs baseline: 1.0551x; 1.0551x over previous
#include <cuda_runtime.h>
#include <cuda_fp16.h>

#define NN 100000
#define EE 3200000
#define FF 128
#define DD 32

// Scratch (device globals: allocation-free rule)
__device__ __align__(128) __half g_t [NN * DD];    // messages, fp16
__device__ __align__(128) float  g_a1[NN * DD];    // layer outputs, PRE-relu
__device__ __align__(128) float  g_a2[NN * DD];
__device__ __align__(128) float  g_a3[NN * DD];
__device__ int g_cnt[NN];
__device__ int g_off[NN + 1];
__device__ int g_cur[NN];
__device__ int g_csr[EE];

// ---------------------------------------------------------------------------
// CSR build: histogram -> single-block scan -> fill
// ---------------------------------------------------------------------------
__global__ __launch_bounds__(256)
void hist_kernel(const int* __restrict__ dst, int* __restrict__ cnt, int E)
{
    int e = blockIdx.x * blockDim.x + threadIdx.x;
    if (e < E) atomicAdd(&cnt[dst[e]], 1);
}

__global__ __launch_bounds__(1024)
void scan_kernel(const int* __restrict__ cnt, int* __restrict__ off,
                 int* __restrict__ cur, int n)
{
    __shared__ int warp_sums[32];
    __shared__ int s_carry;
    const int tid = threadIdx.x;
    if (tid == 0) s_carry = 0;
    __syncthreads();

    for (int base = 0; base < n; base += 1024) {
        const int i = base + tid;
        const int v = (i < n) ? cnt[i] : 0;
        // warp inclusive scan
        int x = v;
        #pragma unroll
        for (int d = 1; d < 32; d <<= 1) {
            int y = __shfl_up_sync(0xffffffffu, x, d);
            if ((tid & 31) >= d) x += y;
        }
        if ((tid & 31) == 31) warp_sums[tid >> 5] = x;
        __syncthreads();
        if (tid < 32) {
            int w = warp_sums[tid];
            #pragma unroll
            for (int d = 1; d < 32; d <<= 1) {
                int y = __shfl_up_sync(0xffffffffu, w, d);
                if (tid >= d) w += y;
            }
            warp_sums[tid] = w;
        }
        __syncthreads();
        const int warp_off = (tid >= 32) ? warp_sums[(tid >> 5) - 1] : 0;
        const int incl = x + warp_off;
        const int excl = incl - v + s_carry;
        if (i < n) { off[i] = excl; cur[i] = excl; }
        __syncthreads();
        if (tid == 1023) s_carry = excl + v;
        __syncthreads();
    }
    if (tid == 0) off[n] = s_carry;
}

__global__ __launch_bounds__(256)
void fill_kernel(const int* __restrict__ src, const int* __restrict__ dst,
                 int* __restrict__ cur, int* __restrict__ csr, int E)
{
    int e = blockIdx.x * blockDim.x + threadIdx.x;
    if (e < E) {
        const int pos = atomicAdd(&cur[dst[e]], 1);
        csr[pos] = src[e];
    }
}

// ---------------------------------------------------------------------------
// Fused transform: for a tile of NODES nodes,
//   t[n]   = half( act(h[n]) @ Wn )
//   agg[n] = act(h[n]) @ Ws + bn        (self term pre-seeds the aggregation)
// 8 threads per node; each thread owns 4 of the 32 output columns.
// ---------------------------------------------------------------------------
template<int DIN, int NODES, bool RELU_IN>
__global__ __launch_bounds__(NODES * 8)
void transform_kernel(const float* __restrict__ hin,
                      const float* __restrict__ Wn,
                      const float* __restrict__ Ws,
                      const float* __restrict__ bn,
                      __half* __restrict__ t,
                      float* __restrict__ agg)
{
    constexpr int THREADS = NODES * 8;
    __shared__ float xs[NODES][DIN + 1];
    __shared__ float wn_s[DIN][32];
    __shared__ float ws_s[DIN][32];

    const int tid   = threadIdx.x;
    const int node0 = blockIdx.x * NODES;

    for (int i = tid; i < DIN * 32; i += THREADS) {
        ((float*)wn_s)[i] = Wn[i];
        ((float*)ws_s)[i] = Ws[i];
    }
    for (int i = tid; i < NODES * DIN; i += THREADS) {
        int r = i / DIN, c = i % DIN;
        float v = hin[(node0 + r) * DIN + c];
        if (RELU_IN) v = fmaxf(v, 0.0f);
        xs[r][c] = v;
    }
    __syncthreads();

    const int ln = tid >> 3;
    const int l8 = tid & 7;
    const int g4 = l8 * 4;

    float4 an = make_float4(0.f, 0.f, 0.f, 0.f);
    float4 as = *(const float4*)(bn + g4);

    #pragma unroll
    for (int k = 0; k < DIN; ++k) {
        const float  xv  = xs[ln][k];
        const float4 wn4 = *(const float4*)&wn_s[k][g4];
        const float4 ws4 = *(const float4*)&ws_s[k][g4];
        an.x = fmaf(xv, wn4.x, an.x);
        an.y = fmaf(xv, wn4.y, an.y);
        an.z = fmaf(xv, wn4.z, an.z);
        an.w = fmaf(xv, wn4.w, an.w);
        as.x = fmaf(xv, ws4.x, as.x);
        as.y = fmaf(xv, ws4.y, as.y);
        as.z = fmaf(xv, ws4.z, as.z);
        as.w = fmaf(xv, ws4.w, as.w);
    }

    const int node = node0 + ln;
    __half2 p0 = __floats2half2_rn(an.x, an.y);
    __half2 p1 = __floats2half2_rn(an.z, an.w);
    uint2 pk;
    pk.x = *(unsigned*)&p0;
    pk.y = *(unsigned*)&p1;
    ((uint2*)t)[node * 8 + l8] = pk;              // 64B row, 8B per lane
    *(float4*)(agg + node * 32 + g4) = as;
}

// ---------------------------------------------------------------------------
// CSR aggregate: agg[n] += sum_{e in in(n)} t[csr_src[e]]
// 8 threads per node (one float4 of columns each), register accumulation.
// ---------------------------------------------------------------------------
__global__ __launch_bounds__(256)
void aggregate_kernel(const int* __restrict__ off, const int* __restrict__ csr,
                      const __half* __restrict__ t, float* __restrict__ agg,
                      int N)
{
    const int tid  = threadIdx.x;
    const int node = blockIdx.x * 32 + (tid >> 3);
    if (node >= N) return;
    const int lane = tid & 7;

    const int beg = off[node];
    const int end = off[node + 1];

    const uint2* tp = (const uint2*)t;

    float ax = 0.f, ay = 0.f, az = 0.f, aw = 0.f;

    int j = beg;
    for (; j + 4 <= end; j += 4) {
        const int s0 = csr[j + 0];
        const int s1 = csr[j + 1];
        const int s2 = csr[j + 2];
        const int s3 = csr[j + 3];
        const uint2 v0 = tp[s0 * 8 + lane];
        const uint2 v1 = tp[s1 * 8 + lane];
        const uint2 v2 = tp[s2 * 8 + lane];
        const uint2 v3 = tp[s3 * 8 + lane];
        #pragma unroll
        for (int q = 0; q < 4; ++q) {
            const uint2 v = (q == 0) ? v0 : (q == 1) ? v1 : (q == 2) ? v2 : v3;
            const float2 f0 = __half22float2(*(const __half2*)&v.x);
            const float2 f1 = __half22float2(*(const __half2*)&v.y);
            ax += f0.x; ay += f0.y; az += f1.x; aw += f1.y;
        }
    }
    for (; j < end; ++j) {
        const uint2 v = tp[csr[j] * 8 + lane];
        const float2 f0 = __half22float2(*(const __half2*)&v.x);
        const float2 f1 = __half22float2(*(const __half2*)&v.y);
        ax += f0.x; ay += f0.y; az += f1.x; aw += f1.y;
    }

    float4* ap = (float4*)(agg + node * 32 + lane * 4);
    float4 seed = *ap;
    seed.x += ax; seed.y += ay; seed.z += az; seed.w += aw;
    *ap = seed;
}

// ---------------------------------------------------------------------------
// Final FC + log_softmax over concat([x, relu(a1), relu(a2), relu(a3)])
// ---------------------------------------------------------------------------
__global__ __launch_bounds__(256)
void fc_kernel(const float* __restrict__ x,
               const float* __restrict__ a1, const float* __restrict__ a2,
               const float* __restrict__ a3,
               const float* __restrict__ fcw, const float* __restrict__ fcb,
               float* __restrict__ out, int N)
{
    __shared__ float w_s[(FF + 3 * DD) * 10];
    for (int i = threadIdx.x; i < (FF + 3 * DD) * 10; i += blockDim.x)
        w_s[i] = fcw[i];
    __syncthreads();

    const int node = blockIdx.x * blockDim.x + threadIdx.x;
    if (node >= N) return;

    float acc[10];
    #pragma unroll
    for (int c = 0; c < 10; ++c) acc[c] = fcb[c];

    int k = 0;
    {
        const float4* r = (const float4*)(x + node * FF);
        for (int q = 0; q < FF / 4; ++q) {
            float4 f4 = r[q];
            float fv[4] = {f4.x, f4.y, f4.z, f4.w};
            #pragma unroll
            for (int j = 0; j < 4; ++j) {
                const float f = fv[j];
                #pragma unroll
                for (int c = 0; c < 10; ++c)
                    acc[c] = fmaf(f, w_s[k * 10 + c], acc[c]);
                ++k;
            }
        }
    }
    const float* const hs[3] = {a1, a2, a3};
    for (int l = 0; l < 3; ++l) {
        const float4* r = (const float4*)(hs[l] + node * DD);
        for (int q = 0; q < DD / 4; ++q) {
            float4 f4 = r[q];
            float fv[4] = {f4.x, f4.y, f4.z, f4.w};
            #pragma unroll
            for (int j = 0; j < 4; ++j) {
                const float f = fmaxf(fv[j], 0.0f);
                #pragma unroll
                for (int c = 0; c < 10; ++c)
                    acc[c] = fmaf(f, w_s[k * 10 + c], acc[c]);
                ++k;
            }
        }
    }

    float m = acc[0];
    #pragma unroll
    for (int c = 1; c < 10; ++c) m = fmaxf(m, acc[c]);
    float s = 0.f;
    #pragma unroll
    for (int c = 0; c < 10; ++c) s += expf(acc[c] - m);
    const float lse = m + logf(s);
    #pragma unroll
    for (int c = 0; c < 10; ++c) out[node * 10 + c] = acc[c] - lse;
}

// ---------------------------------------------------------------------------
extern "C" void kernel_launch(void* const* d_in, const int* in_sizes, int n_in,
                              void* d_out, int out_size)
{
    const float* x   = (const float*)d_in[0];
    const int*   src = (const int*)  d_in[1];
    const int*   dst = (const int*)  d_in[2];
    const float* Wn0 = (const float*)d_in[3];
    const float* bn0 = (const float*)d_in[4];
    const float* Ws0 = (const float*)d_in[5];
    const float* Wn1 = (const float*)d_in[6];
    const float* bn1 = (const float*)d_in[7];
    const float* Ws1 = (const float*)d_in[8];
    const float* Wn2 = (const float*)d_in[9];
    const float* bn2 = (const float*)d_in[10];
    const float* Ws2 = (const float*)d_in[11];
    const float* fcw = (const float*)d_in[12];
    const float* fcb = (const float*)d_in[13];
    float* out = (float*)d_out;

    const int N = in_sizes[0] / FF;
    const int E = in_sizes[1];

    __half* t;
    float *a1, *a2, *a3;
    int *cnt, *off, *cur, *csr;
    cudaGetSymbolAddress((void**)&t,   g_t);
    cudaGetSymbolAddress((void**)&a1,  g_a1);
    cudaGetSymbolAddress((void**)&a2,  g_a2);
    cudaGetSymbolAddress((void**)&a3,  g_a3);
    cudaGetSymbolAddress((void**)&cnt, g_cnt);
    cudaGetSymbolAddress((void**)&off, g_off);
    cudaGetSymbolAddress((void**)&cur, g_cur);
    cudaGetSymbolAddress((void**)&csr, g_csr);

    const int eb = (E + 255) / 256;
    const int nb32 = (N + 31) / 32;

    // Build CSR (dst-grouped) — shared by all 3 aggregation passes
    cudaMemsetAsync(cnt, 0, N * sizeof(int));
    hist_kernel<<<eb, 256>>>(dst, cnt, E);
    scan_kernel<<<1, 1024>>>(cnt, off, cur, N);
    fill_kernel<<<eb, 256>>>(src, dst, cur, csr, E);

    // Layer 0 (din = 128, input is raw x)
    transform_kernel<FF, 16, false><<<N / 16, 128>>>(x, Wn0, Ws0, bn0, t, a1);
    aggregate_kernel<<<nb32, 256>>>(off, csr, t, a1, N);

    // Layer 1 (din = 32, relu applied when reading pre-activation a1)
    transform_kernel<DD, 32, true><<<N / 32, 256>>>(a1, Wn1, Ws1, bn1, t, a2);
    aggregate_kernel<<<nb32, 256>>>(off, csr, t, a2, N);

    // Layer 2
    transform_kernel<DD, 32, true><<<N / 32, 256>>>(a2, Wn2, Ws2, bn2, t, a3);
    aggregate_kernel<<<nb32, 256>>>(off, csr, t, a3, N);

    // FC + log_softmax
    fc_kernel<<<(N + 255) / 256, 256>>>(x, a1, a2, a3, fcw, fcb, out, N);
}

// round 3
// speedup vs baseline: 1.4913x; 1.4135x over previous
#include <cuda_runtime.h>
#include <cuda_fp16.h>
#include <mma.h>

using namespace nvcuda;

#define NN 100000
#define EE 3200000
#define FF 128
#define DD 32

// Scratch (device globals: allocation-free rule)
__device__ __align__(128) __half g_t [NN * DD];    // messages, fp16
__device__ __align__(128) float  g_a1[NN * DD];    // layer outputs, PRE-relu
__device__ __align__(128) float  g_a2[NN * DD];
__device__ __align__(128) float  g_a3[NN * DD];
__device__ int g_cnt[NN];
__device__ int g_off[NN + 1];
__device__ int g_cur[NN];
__device__ int g_csr[EE];

// ---------------------------------------------------------------------------
// CSR build: histogram -> single-block scan -> fill
// ---------------------------------------------------------------------------
__global__ __launch_bounds__(256)
void hist_kernel(const int* __restrict__ dst, int* __restrict__ cnt, int E)
{
    int e = blockIdx.x * blockDim.x + threadIdx.x;
    if (e < E) atomicAdd(&cnt[dst[e]], 1);
}

__global__ __launch_bounds__(1024)
void scan_kernel(const int* __restrict__ cnt, int* __restrict__ off,
                 int* __restrict__ cur, int n)
{
    __shared__ int warp_sums[32];
    __shared__ int s_carry;
    const int tid = threadIdx.x;
    if (tid == 0) s_carry = 0;
    __syncthreads();

    for (int base = 0; base < n; base += 1024) {
        const int i = base + tid;
        const int v = (i < n) ? cnt[i] : 0;
        int x = v;
        #pragma unroll
        for (int d = 1; d < 32; d <<= 1) {
            int y = __shfl_up_sync(0xffffffffu, x, d);
            if ((tid & 31) >= d) x += y;
        }
        if ((tid & 31) == 31) warp_sums[tid >> 5] = x;
        __syncthreads();
        if (tid < 32) {
            int w = warp_sums[tid];
            #pragma unroll
            for (int d = 1; d < 32; d <<= 1) {
                int y = __shfl_up_sync(0xffffffffu, w, d);
                if (tid >= d) w += y;
            }
            warp_sums[tid] = w;
        }
        __syncthreads();
        const int warp_off = (tid >= 32) ? warp_sums[(tid >> 5) - 1] : 0;
        const int incl = x + warp_off;
        const int excl = incl - v + s_carry;
        if (i < n) { off[i] = excl; cur[i] = excl; }
        __syncthreads();
        if (tid == 1023) s_carry = excl + v;
        __syncthreads();
    }
    if (tid == 0) off[n] = s_carry;
}

__global__ __launch_bounds__(256)
void fill_kernel(const int* __restrict__ src, const int* __restrict__ dst,
                 int* __restrict__ cur, int* __restrict__ csr, int E)
{
    int e = blockIdx.x * blockDim.x + threadIdx.x;
    if (e < E) {
        const int pos = atomicAdd(&cur[dst[e]], 1);
        csr[pos] = src[e];
    }
}

// ---------------------------------------------------------------------------
// Tensor-core fused transform (wmma fp16, fp32 accumulate):
//   t[n]   = half( act(h[n]) @ Wn )
//   agg[n] = act(h[n]) @ Ws + bn
// Block = 256 threads / 8 warps, M-tile = 128 rows, N = 64 (Wn|Ws), K = DIN.
// x converted fp32->fp16 during smem staging (no extra pass).
// ---------------------------------------------------------------------------
template<int DIN, bool RELU_IN>
__global__ __launch_bounds__(256)
void mma_transform(const float* __restrict__ hin,
                   const float* __restrict__ Wn,
                   const float* __restrict__ Ws,
                   const float* __restrict__ bn,
                   __half* __restrict__ t,
                   float* __restrict__ agg, int N)
{
    constexpr int KC    = (DIN > 64) ? 64 : DIN;   // K chunk staged at a time
    constexpr int XS_LD = KC + 8;                  // halves
    constexpr int B_LD  = 72;                      // halves (64 + 8 pad)
    constexpr int CS_LD = 68;                      // floats (64 + 4 pad)
    constexpr unsigned S_STAGE = 128u * XS_LD * 2u + (unsigned)DIN * B_LD * 2u;
    constexpr unsigned S_EPI   = 128u * CS_LD * 4u;
    constexpr unsigned S_BYTES = (S_STAGE > S_EPI) ? S_STAGE : S_EPI;

    __shared__ __align__(32) unsigned char sraw[S_BYTES];
    __half* xs = (__half*)sraw;
    __half* bs = (__half*)(sraw + 128u * XS_LD * 2u);
    float*  cs = (float*)sraw;

    const int tid  = threadIdx.x;
    const int wid  = tid >> 5;
    const int row0 = blockIdx.x * 128;

    // Stage combined weight matrix B = [Wn | Ws] as fp16: [DIN][64]
    for (int i = tid; i < DIN * 32; i += 256) {
        const int k = i / 32, j = i % 32;
        bs[k * B_LD + j]      = __float2half(Wn[i]);
        bs[k * B_LD + 32 + j] = __float2half(Ws[i]);
    }

    wmma::fragment<wmma::accumulator, 16, 16, 16, float> c[4];
    #pragma unroll
    for (int j = 0; j < 4; ++j) wmma::fill_fragment(c[j], 0.0f);

    const int m0 = wid * 16;

    for (int kc = 0; kc < DIN; kc += KC) {
        __syncthreads();   // xs reuse across chunks; also orders bs before mma
        for (int i = tid; i < 128 * KC; i += 256) {
            const int r = i / KC, k = i % KC;
            const int grow = row0 + r;
            float v = (grow < N) ? hin[grow * DIN + kc + k] : 0.0f;
            if (RELU_IN) v = fmaxf(v, 0.0f);
            xs[r * XS_LD + k] = __float2half(v);
        }
        __syncthreads();

        #pragma unroll
        for (int k0 = 0; k0 < KC; k0 += 16) {
            wmma::fragment<wmma::matrix_a, 16, 16, 16, __half, wmma::row_major> a;
            wmma::load_matrix_sync(a, xs + m0 * XS_LD + k0, XS_LD);
            #pragma unroll
            for (int j = 0; j < 4; ++j) {
                wmma::fragment<wmma::matrix_b, 16, 16, 16, __half, wmma::row_major> b;
                wmma::load_matrix_sync(b, bs + (kc + k0) * B_LD + j * 16, B_LD);
                wmma::mma_sync(c[j], a, b, c[j]);
            }
        }
    }

    __syncthreads();   // done reading xs/bs; overlay epilogue buffer
    #pragma unroll
    for (int j = 0; j < 4; ++j)
        wmma::store_matrix_sync(cs + m0 * CS_LD + j * 16, c[j], CS_LD,
                                wmma::mem_row_major);
    __syncthreads();

    // Write messages t (cols 0..31) as half2
    for (int i = tid; i < 128 * 16; i += 256) {
        const int r = i / 16, c2 = i % 16;
        const int node = row0 + r;
        if (node < N) {
            __half2 h = __floats2half2_rn(cs[r * CS_LD + 2 * c2],
                                          cs[r * CS_LD + 2 * c2 + 1]);
            ((__half2*)t)[node * 16 + c2] = h;
        }
    }
    // Write agg seed (cols 32..63) + bias as float4
    for (int i = tid; i < 128 * 8; i += 256) {
        const int r = i / 8, c4 = i % 8;
        const int node = row0 + r;
        if (node < N) {
            float4 v;
            v.x = cs[r * CS_LD + 32 + c4 * 4 + 0] + bn[c4 * 4 + 0];
            v.y = cs[r * CS_LD + 32 + c4 * 4 + 1] + bn[c4 * 4 + 1];
            v.z = cs[r * CS_LD + 32 + c4 * 4 + 2] + bn[c4 * 4 + 2];
            v.w = cs[r * CS_LD + 32 + c4 * 4 + 3] + bn[c4 * 4 + 3];
            *(float4*)(agg + node * 32 + c4 * 4) = v;
        }
    }
}

// ---------------------------------------------------------------------------
// CSR aggregate: agg[n] += sum_{e in in(n)} t[csr_src[e]]
// 8 threads per node (one float4 of columns each), register accumulation.
// ---------------------------------------------------------------------------
__global__ __launch_bounds__(256)
void aggregate_kernel(const int* __restrict__ off, const int* __restrict__ csr,
                      const __half* __restrict__ t, float* __restrict__ agg,
                      int N)
{
    const int tid  = threadIdx.x;
    const int node = blockIdx.x * 32 + (tid >> 3);
    if (node >= N) return;
    const int lane = tid & 7;

    const int beg = off[node];
    const int end = off[node + 1];

    const uint2* tp = (const uint2*)t;

    float ax = 0.f, ay = 0.f, az = 0.f, aw = 0.f;

    int j = beg;
    for (; j + 4 <= end; j += 4) {
        const int s0 = csr[j + 0];
        const int s1 = csr[j + 1];
        const int s2 = csr[j + 2];
        const int s3 = csr[j + 3];
        const uint2 v0 = tp[s0 * 8 + lane];
        const uint2 v1 = tp[s1 * 8 + lane];
        const uint2 v2 = tp[s2 * 8 + lane];
        const uint2 v3 = tp[s3 * 8 + lane];
        #pragma unroll
        for (int q = 0; q < 4; ++q) {
            const uint2 v = (q == 0) ? v0 : (q == 1) ? v1 : (q == 2) ? v2 : v3;
            const float2 f0 = __half22float2(*(const __half2*)&v.x);
            const float2 f1 = __half22float2(*(const __half2*)&v.y);
            ax += f0.x; ay += f0.y; az += f1.x; aw += f1.y;
        }
    }
    for (; j < end; ++j) {
        const uint2 v = tp[csr[j] * 8 + lane];
        const float2 f0 = __half22float2(*(const __half2*)&v.x);
        const float2 f1 = __half22float2(*(const __half2*)&v.y);
        ax += f0.x; ay += f0.y; az += f1.x; aw += f1.y;
    }

    float4* ap = (float4*)(agg + node * 32 + lane * 4);
    float4 seed = *ap;
    seed.x += ax; seed.y += ay; seed.z += az; seed.w += aw;
    *ap = seed;
}

// ---------------------------------------------------------------------------
// Final FC + log_softmax over concat([x, relu(a1), relu(a2), relu(a3)])
// ---------------------------------------------------------------------------
__global__ __launch_bounds__(256)
void fc_kernel(const float* __restrict__ x,
               const float* __restrict__ a1, const float* __restrict__ a2,
               const float* __restrict__ a3,
               const float* __restrict__ fcw, const float* __restrict__ fcb,
               float* __restrict__ out, int N)
{
    __shared__ float w_s[(FF + 3 * DD) * 10];
    for (int i = threadIdx.x; i < (FF + 3 * DD) * 10; i += blockDim.x)
        w_s[i] = fcw[i];
    __syncthreads();

    const int node = blockIdx.x * blockDim.x + threadIdx.x;
    if (node >= N) return;

    float acc[10];
    #pragma unroll
    for (int c = 0; c < 10; ++c) acc[c] = fcb[c];

    int k = 0;
    {
        const float4* r = (const float4*)(x + node * FF);
        for (int q = 0; q < FF / 4; ++q) {
            float4 f4 = r[q];
            float fv[4] = {f4.x, f4.y, f4.z, f4.w};
            #pragma unroll
            for (int j = 0; j < 4; ++j) {
                const float f = fv[j];
                #pragma unroll
                for (int c = 0; c < 10; ++c)
                    acc[c] = fmaf(f, w_s[k * 10 + c], acc[c]);
                ++k;
            }
        }
    }
    const float* const hs[3] = {a1, a2, a3};
    for (int l = 0; l < 3; ++l) {
        const float4* r = (const float4*)(hs[l] + node * DD);
        for (int q = 0; q < DD / 4; ++q) {
            float4 f4 = r[q];
            float fv[4] = {f4.x, f4.y, f4.z, f4.w};
            #pragma unroll
            for (int j = 0; j < 4; ++j) {
                const float f = fmaxf(fv[j], 0.0f);
                #pragma unroll
                for (int c = 0; c < 10; ++c)
                    acc[c] = fmaf(f, w_s[k * 10 + c], acc[c]);
                ++k;
            }
        }
    }

    float m = acc[0];
    #pragma unroll
    for (int c = 1; c < 10; ++c) m = fmaxf(m, acc[c]);
    float s = 0.f;
    #pragma unroll
    for (int c = 0; c < 10; ++c) s += expf(acc[c] - m);
    const float lse = m + logf(s);
    #pragma unroll
    for (int c = 0; c < 10; ++c) out[node * 10 + c] = acc[c] - lse;
}

// ---------------------------------------------------------------------------
extern "C" void kernel_launch(void* const* d_in, const int* in_sizes, int n_in,
                              void* d_out, int out_size)
{
    const float* x   = (const float*)d_in[0];
    const int*   src = (const int*)  d_in[1];
    const int*   dst = (const int*)  d_in[2];
    const float* Wn0 = (const float*)d_in[3];
    const float* bn0 = (const float*)d_in[4];
    const float* Ws0 = (const float*)d_in[5];
    const float* Wn1 = (const float*)d_in[6];
    const float* bn1 = (const float*)d_in[7];
    const float* Ws1 = (const float*)d_in[8];
    const float* Wn2 = (const float*)d_in[9];
    const float* bn2 = (const float*)d_in[10];
    const float* Ws2 = (const float*)d_in[11];
    const float* fcw = (const float*)d_in[12];
    const float* fcb = (const float*)d_in[13];
    float* out = (float*)d_out;

    const int N = in_sizes[0] / FF;
    const int E = in_sizes[1];

    __half* t;
    float *a1, *a2, *a3;
    int *cnt, *off, *cur, *csr;
    cudaGetSymbolAddress((void**)&t,   g_t);
    cudaGetSymbolAddress((void**)&a1,  g_a1);
    cudaGetSymbolAddress((void**)&a2,  g_a2);
    cudaGetSymbolAddress((void**)&a3,  g_a3);
    cudaGetSymbolAddress((void**)&cnt, g_cnt);
    cudaGetSymbolAddress((void**)&off, g_off);
    cudaGetSymbolAddress((void**)&cur, g_cur);
    cudaGetSymbolAddress((void**)&csr, g_csr);

    const int eb   = (E + 255) / 256;
    const int nb32 = (N + 31) / 32;
    const int tb   = (N + 127) / 128;

    // Build CSR (dst-grouped) — shared by all 3 aggregation passes
    cudaMemsetAsync(cnt, 0, N * sizeof(int));
    hist_kernel<<<eb, 256>>>(dst, cnt, E);
    scan_kernel<<<1, 1024>>>(cnt, off, cur, N);
    fill_kernel<<<eb, 256>>>(src, dst, cur, csr, E);

    // Layer 0 (din = 128, input is raw x)
    mma_transform<FF, false><<<tb, 256>>>(x, Wn0, Ws0, bn0, t, a1, N);
    aggregate_kernel<<<nb32, 256>>>(off, csr, t, a1, N);

    // Layer 1 (din = 32, relu applied when reading pre-activation a1)
    mma_transform<DD, true><<<tb, 256>>>(a1, Wn1, Ws1, bn1, t, a2, N);
    aggregate_kernel<<<nb32, 256>>>(off, csr, t, a2, N);

    // Layer 2
    mma_transform<DD, true><<<tb, 256>>>(a2, Wn2, Ws2, bn2, t, a3, N);
    aggregate_kernel<<<nb32, 256>>>(off, csr, t, a3, N);

    // FC + log_softmax
    fc_kernel<<<(N + 255) / 256, 256>>>(x, a1, a2, a3, fcw, fcb, out, N);
}

// round 4
// speedup vs baseline: 2.1096x; 1.4146x over previous
#include <cuda_runtime.h>
#include <cuda_fp16.h>
#include <mma.h>

using namespace nvcuda;

#define NN 100000
#define EE 3200000
#define FF 128
#define DD 32
#define SCAN_B 1024
#define SCAN_NB ((NN + SCAN_B - 1) / SCAN_B)   // 98

// Scratch (device globals: allocation-free rule)
__device__ __align__(128) __half g_t [NN * DD];    // messages, fp16
__device__ __align__(128) float  g_a1[NN * DD];    // layer outputs, PRE-relu
__device__ __align__(128) float  g_a2[NN * DD];
__device__ __align__(128) float  g_a3[NN * DD];
__device__ __align__(128) float  g_p [NN * 16];    // partial logits x@fcw_x
__device__ int g_cnt[NN];
__device__ int g_off[NN + 1];
__device__ int g_cur[NN];
__device__ int g_csr[EE];
__device__ int g_bsum[SCAN_NB];

// ---------------------------------------------------------------------------
// CSR build: histogram -> 3-phase parallel scan -> fill
// ---------------------------------------------------------------------------
__global__ __launch_bounds__(256)
void hist_kernel(const int* __restrict__ dst, int* __restrict__ cnt, int E)
{
    int e = blockIdx.x * blockDim.x + threadIdx.x;
    if (e < E) atomicAdd(&cnt[dst[e]], 1);
}

// Phase A: per-block local exclusive scan into off, block total into bsum
__global__ __launch_bounds__(SCAN_B)
void scanA_kernel(const int* __restrict__ cnt, int* __restrict__ off,
                  int* __restrict__ bsum, int n)
{
    __shared__ int warp_sums[32];
    const int tid = threadIdx.x;
    const int i = blockIdx.x * SCAN_B + tid;
    const int v = (i < n) ? cnt[i] : 0;

    int x = v;
    #pragma unroll
    for (int d = 1; d < 32; d <<= 1) {
        int y = __shfl_up_sync(0xffffffffu, x, d);
        if ((tid & 31) >= d) x += y;
    }
    if ((tid & 31) == 31) warp_sums[tid >> 5] = x;
    __syncthreads();
    if (tid < 32) {
        int w = warp_sums[tid];
        #pragma unroll
        for (int d = 1; d < 32; d <<= 1) {
            int y = __shfl_up_sync(0xffffffffu, w, d);
            if (tid >= d) w += y;
        }
        warp_sums[tid] = w;
    }
    __syncthreads();
    const int warp_off = (tid >= 32) ? warp_sums[(tid >> 5) - 1] : 0;
    const int excl = x + warp_off - v;
    if (i < n) off[i] = excl;
    if (tid == SCAN_B - 1) bsum[blockIdx.x] = excl + v;
}

// Phase B: exclusive scan of block sums (single small block)
__global__ __launch_bounds__(128)
void scanB_kernel(int* __restrict__ bsum, int* __restrict__ off, int n)
{
    __shared__ int s[SCAN_NB];
    const int tid = threadIdx.x;
    if (tid < SCAN_NB) s[tid] = bsum[tid];
    __syncthreads();
    if (tid == 0) {
        int run = 0;
        #pragma unroll 4
        for (int b = 0; b < SCAN_NB; ++b) {
            int v = s[b];
            s[b] = run;
            run += v;
        }
        off[n] = run;
    }
    __syncthreads();
    if (tid < SCAN_NB) bsum[tid] = s[tid];
}

// Phase C: add block prefix, mirror into cur
__global__ __launch_bounds__(SCAN_B)
void scanC_kernel(int* __restrict__ off, int* __restrict__ cur,
                  const int* __restrict__ bsum, int n)
{
    const int i = blockIdx.x * SCAN_B + threadIdx.x;
    if (i < n) {
        const int o = off[i] + bsum[blockIdx.x];
        off[i] = o;
        cur[i] = o;
    }
}

__global__ __launch_bounds__(256)
void fill_kernel(const int* __restrict__ src, const int* __restrict__ dst,
                 int* __restrict__ cur, int* __restrict__ csr, int E)
{
    int e = blockIdx.x * blockDim.x + threadIdx.x;
    if (e < E) {
        const int pos = atomicAdd(&cur[dst[e]], 1);
        csr[pos] = src[e];
    }
}

// ---------------------------------------------------------------------------
// Tensor-core fused transform (wmma fp16, fp32 accumulate):
//   B = [Wn | Ws]                 (NCOL=64) or
//   B = [Wn | Ws | fcw_x pad16]   (NCOL=80, layer 0 only)
//   t[n]   = half( act(h[n]) @ Wn )
//   agg[n] = act(h[n]) @ Ws + bn
//   p[n]   = act(h[n]) @ fcw_x          (partial logits, layer 0)
// Block = 256 thr / 8 warps, M-tile = 128 rows. float4 input staging.
// ---------------------------------------------------------------------------
template<int DIN, int NCOL, bool RELU_IN>
__global__ __launch_bounds__(256)
void mma_transform(const float* __restrict__ hin,
                   const float* __restrict__ Wn,
                   const float* __restrict__ Ws,
                   const float* __restrict__ bn,
                   const float* __restrict__ fcw,   // may be null when NCOL==64
                   __half* __restrict__ t,
                   float* __restrict__ agg,
                   float* __restrict__ p, int N)
{
    constexpr int KC    = (DIN > 64) ? 64 : DIN;   // K chunk staged at a time
    constexpr int XS_LD = KC + 8;                  // halves
    constexpr int B_LD  = NCOL + 8;                // halves
    constexpr int CS_LD = NCOL + 4;                // floats
    constexpr int NFRAG = NCOL / 16;
    constexpr unsigned S_STAGE = 128u * XS_LD * 2u + (unsigned)DIN * B_LD * 2u;
    constexpr unsigned S_EPI   = 128u * CS_LD * 4u;
    constexpr unsigned S_BYTES = (S_STAGE > S_EPI) ? S_STAGE : S_EPI;

    __shared__ __align__(32) unsigned char sraw[S_BYTES];
    __half* xs = (__half*)sraw;
    __half* bs = (__half*)(sraw + 128u * XS_LD * 2u);
    float*  cs = (float*)sraw;

    const int tid  = threadIdx.x;
    const int wid  = tid >> 5;
    const int row0 = blockIdx.x * 128;

    // Stage combined weight matrix B as fp16: [DIN][NCOL]
    for (int i = tid; i < DIN * 32; i += 256) {
        const int k = i / 32, j = i % 32;
        bs[k * B_LD + j]      = __float2half(Wn[i]);
        bs[k * B_LD + 32 + j] = __float2half(Ws[i]);
    }
    if (NCOL == 80) {
        for (int i = tid; i < DIN * 16; i += 256) {
            const int k = i / 16, c = i % 16;
            bs[k * B_LD + 64 + c] = (c < 10) ? __float2half(fcw[k * 10 + c])
                                             : __float2half(0.0f);
        }
    }

    wmma::fragment<wmma::accumulator, 16, 16, 16, float> c[NFRAG];
    #pragma unroll
    for (int j = 0; j < NFRAG; ++j) wmma::fill_fragment(c[j], 0.0f);

    const int m0 = wid * 16;

    for (int kc = 0; kc < DIN; kc += KC) {
        __syncthreads();   // xs reuse across chunks; also orders bs before mma
        // float4 staging: KC/4 float4 per row
        constexpr int Q = KC / 4;
        const float4* h4 = (const float4*)hin;
        for (int i = tid; i < 128 * Q; i += 256) {
            const int r = i / Q, q = i % Q;
            const int grow = row0 + r;
            float4 v = make_float4(0.f, 0.f, 0.f, 0.f);
            if (grow < N) v = h4[grow * (DIN / 4) + kc / 4 + q];
            if (RELU_IN) {
                v.x = fmaxf(v.x, 0.f); v.y = fmaxf(v.y, 0.f);
                v.z = fmaxf(v.z, 0.f); v.w = fmaxf(v.w, 0.f);
            }
            __half2 h0 = __floats2half2_rn(v.x, v.y);
            __half2 h1 = __floats2half2_rn(v.z, v.w);
            uint2 pk;
            pk.x = *(unsigned*)&h0;
            pk.y = *(unsigned*)&h1;
            *(uint2*)(xs + r * XS_LD + q * 4) = pk;
        }
        __syncthreads();

        #pragma unroll
        for (int k0 = 0; k0 < KC; k0 += 16) {
            wmma::fragment<wmma::matrix_a, 16, 16, 16, __half, wmma::row_major> a;
            wmma::load_matrix_sync(a, xs + m0 * XS_LD + k0, XS_LD);
            #pragma unroll
            for (int j = 0; j < NFRAG; ++j) {
                wmma::fragment<wmma::matrix_b, 16, 16, 16, __half, wmma::row_major> b;
                wmma::load_matrix_sync(b, bs + (kc + k0) * B_LD + j * 16, B_LD);
                wmma::mma_sync(c[j], a, b, c[j]);
            }
        }
    }

    __syncthreads();   // done reading xs/bs; overlay epilogue buffer
    #pragma unroll
    for (int j = 0; j < NFRAG; ++j)
        wmma::store_matrix_sync(cs + m0 * CS_LD + j * 16, c[j], CS_LD,
                                wmma::mem_row_major);
    __syncthreads();

    // Write messages t (cols 0..31) as half2
    for (int i = tid; i < 128 * 16; i += 256) {
        const int r = i / 16, c2 = i % 16;
        const int node = row0 + r;
        if (node < N) {
            __half2 h = __floats2half2_rn(cs[r * CS_LD + 2 * c2],
                                          cs[r * CS_LD + 2 * c2 + 1]);
            ((__half2*)t)[node * 16 + c2] = h;
        }
    }
    // Write agg seed (cols 32..63) + bias as float4
    for (int i = tid; i < 128 * 8; i += 256) {
        const int r = i / 8, c4 = i % 8;
        const int node = row0 + r;
        if (node < N) {
            float4 v;
            v.x = cs[r * CS_LD + 32 + c4 * 4 + 0] + bn[c4 * 4 + 0];
            v.y = cs[r * CS_LD + 32 + c4 * 4 + 1] + bn[c4 * 4 + 1];
            v.z = cs[r * CS_LD + 32 + c4 * 4 + 2] + bn[c4 * 4 + 2];
            v.w = cs[r * CS_LD + 32 + c4 * 4 + 3] + bn[c4 * 4 + 3];
            *(float4*)(agg + node * 32 + c4 * 4) = v;
        }
    }
    // Write partial logits p (cols 64..79) as float4 (layer 0 only)
    if (NCOL == 80) {
        for (int i = tid; i < 128 * 4; i += 256) {
            const int r = i / 4, q = i % 4;
            const int node = row0 + r;
            if (node < N) {
                float4 v;
                v.x = cs[r * CS_LD + 64 + q * 4 + 0];
                v.y = cs[r * CS_LD + 64 + q * 4 + 1];
                v.z = cs[r * CS_LD + 64 + q * 4 + 2];
                v.w = cs[r * CS_LD + 64 + q * 4 + 3];
                *(float4*)(p + node * 16 + q * 4) = v;
            }
        }
    }
}

// ---------------------------------------------------------------------------
// CSR aggregate: agg[n] += sum_{e in in(n)} t[csr_src[e]]
// 4 threads per node, one uint4 (16B = 8 half cols) each; fp32 accumulation.
// ---------------------------------------------------------------------------
__global__ __launch_bounds__(256)
void aggregate_kernel(const int* __restrict__ off, const int* __restrict__ csr,
                      const __half* __restrict__ t, float* __restrict__ agg,
                      int N)
{
    const int tid  = threadIdx.x;
    const int node = blockIdx.x * 64 + (tid >> 2);
    if (node >= N) return;
    const int lane = tid & 3;

    const int beg = off[node];
    const int end = off[node + 1];

    const uint4* tp = (const uint4*)t;   // 4 x uint4 per 32-half row

    float a0 = 0.f, a1 = 0.f, a2 = 0.f, a3 = 0.f;
    float a4 = 0.f, a5 = 0.f, a6 = 0.f, a7 = 0.f;

    int j = beg;
    for (; j + 4 <= end; j += 4) {
        const int s0 = csr[j + 0];
        const int s1 = csr[j + 1];
        const int s2 = csr[j + 2];
        const int s3 = csr[j + 3];
        const uint4 v0 = tp[s0 * 4 + lane];
        const uint4 v1 = tp[s1 * 4 + lane];
        const uint4 v2 = tp[s2 * 4 + lane];
        const uint4 v3 = tp[s3 * 4 + lane];
        #pragma unroll
        for (int q = 0; q < 4; ++q) {
            const uint4 v = (q == 0) ? v0 : (q == 1) ? v1 : (q == 2) ? v2 : v3;
            const float2 f0 = __half22float2(*(const __half2*)&v.x);
            const float2 f1 = __half22float2(*(const __half2*)&v.y);
            const float2 f2 = __half22float2(*(const __half2*)&v.z);
            const float2 f3 = __half22float2(*(const __half2*)&v.w);
            a0 += f0.x; a1 += f0.y; a2 += f1.x; a3 += f1.y;
            a4 += f2.x; a5 += f2.y; a6 += f3.x; a7 += f3.y;
        }
    }
    for (; j < end; ++j) {
        const uint4 v = tp[csr[j] * 4 + lane];
        const float2 f0 = __half22float2(*(const __half2*)&v.x);
        const float2 f1 = __half22float2(*(const __half2*)&v.y);
        const float2 f2 = __half22float2(*(const __half2*)&v.z);
        const float2 f3 = __half22float2(*(const __half2*)&v.w);
        a0 += f0.x; a1 += f0.y; a2 += f1.x; a3 += f1.y;
        a4 += f2.x; a5 += f2.y; a6 += f3.x; a7 += f3.y;
    }

    float4* ap = (float4*)(agg + node * 32 + lane * 8);
    float4 s0 = ap[0], s1 = ap[1];
    s0.x += a0; s0.y += a1; s0.z += a2; s0.w += a3;
    s1.x += a4; s1.y += a5; s1.z += a6; s1.w += a7;
    ap[0] = s0; ap[1] = s1;
}

// ---------------------------------------------------------------------------
// Final FC (hidden segments only; x segment pre-fused into p) + log_softmax
// logits = p + sum_l relu(a_l) @ fcw_hidden_l + fcb
// ---------------------------------------------------------------------------
__global__ __launch_bounds__(256)
void fc_kernel(const float* __restrict__ p,
               const float* __restrict__ a1, const float* __restrict__ a2,
               const float* __restrict__ a3,
               const float* __restrict__ fcw, const float* __restrict__ fcb,
               float* __restrict__ out, int N)
{
    __shared__ float w_s[3 * DD * 10];   // hidden-segment weights (960)
    __shared__ float b_s[10];
    for (int i = threadIdx.x; i < 3 * DD * 10; i += blockDim.x)
        w_s[i] = fcw[FF * 10 + i];
    if (threadIdx.x < 10) b_s[threadIdx.x] = fcb[threadIdx.x];
    __syncthreads();

    const int node = blockIdx.x * blockDim.x + threadIdx.x;
    if (node >= N) return;

    float acc[10];
    {
        const float4* pr = (const float4*)(p + node * 16);
        const float4 p0 = pr[0], p1 = pr[1];
        const float2 p2 = *(const float2*)(p + node * 16 + 8);
        acc[0] = p0.x + b_s[0]; acc[1] = p0.y + b_s[1];
        acc[2] = p0.z + b_s[2]; acc[3] = p0.w + b_s[3];
        acc[4] = p1.x + b_s[4]; acc[5] = p1.y + b_s[5];
        acc[6] = p1.z + b_s[6]; acc[7] = p1.w + b_s[7];
        acc[8] = p2.x + b_s[8]; acc[9] = p2.y + b_s[9];
    }

    const float* const hs[3] = {a1, a2, a3};
    int k = 0;
    #pragma unroll
    for (int l = 0; l < 3; ++l) {
        const float4* r = (const float4*)(hs[l] + node * DD);
        #pragma unroll
        for (int q = 0; q < DD / 4; ++q) {
            float4 f4 = r[q];
            float fv[4] = {f4.x, f4.y, f4.z, f4.w};
            #pragma unroll
            for (int j = 0; j < 4; ++j) {
                const float f = fmaxf(fv[j], 0.0f);
                #pragma unroll
                for (int c = 0; c < 10; ++c)
                    acc[c] = fmaf(f, w_s[k * 10 + c], acc[c]);
                ++k;
            }
        }
    }

    float m = acc[0];
    #pragma unroll
    for (int c = 1; c < 10; ++c) m = fmaxf(m, acc[c]);
    float s = 0.f;
    #pragma unroll
    for (int c = 0; c < 10; ++c) s += expf(acc[c] - m);
    const float lse = m + logf(s);
    #pragma unroll
    for (int c = 0; c < 10; ++c) out[node * 10 + c] = acc[c] - lse;
}

// ---------------------------------------------------------------------------
extern "C" void kernel_launch(void* const* d_in, const int* in_sizes, int n_in,
                              void* d_out, int out_size)
{
    const float* x   = (const float*)d_in[0];
    const int*   src = (const int*)  d_in[1];
    const int*   dst = (const int*)  d_in[2];
    const float* Wn0 = (const float*)d_in[3];
    const float* bn0 = (const float*)d_in[4];
    const float* Ws0 = (const float*)d_in[5];
    const float* Wn1 = (const float*)d_in[6];
    const float* bn1 = (const float*)d_in[7];
    const float* Ws1 = (const float*)d_in[8];
    const float* Wn2 = (const float*)d_in[9];
    const float* bn2 = (const float*)d_in[10];
    const float* Ws2 = (const float*)d_in[11];
    const float* fcw = (const float*)d_in[12];
    const float* fcb = (const float*)d_in[13];
    float* out = (float*)d_out;

    const int N = in_sizes[0] / FF;
    const int E = in_sizes[1];

    __half* t;
    float *a1, *a2, *a3, *p;
    int *cnt, *off, *cur, *csr, *bsum;
    cudaGetSymbolAddress((void**)&t,    g_t);
    cudaGetSymbolAddress((void**)&a1,   g_a1);
    cudaGetSymbolAddress((void**)&a2,   g_a2);
    cudaGetSymbolAddress((void**)&a3,   g_a3);
    cudaGetSymbolAddress((void**)&p,    g_p);
    cudaGetSymbolAddress((void**)&cnt,  g_cnt);
    cudaGetSymbolAddress((void**)&off,  g_off);
    cudaGetSymbolAddress((void**)&cur,  g_cur);
    cudaGetSymbolAddress((void**)&csr,  g_csr);
    cudaGetSymbolAddress((void**)&bsum, g_bsum);

    const int eb   = (E + 255) / 256;
    const int nb64 = (N + 63) / 64;
    const int tb   = (N + 127) / 128;
    const int snb  = (N + SCAN_B - 1) / SCAN_B;

    // Build CSR (dst-grouped) — shared by all 3 aggregation passes
    cudaMemsetAsync(cnt, 0, N * sizeof(int));
    hist_kernel<<<eb, 256>>>(dst, cnt, E);
    scanA_kernel<<<snb, SCAN_B>>>(cnt, off, bsum, N);
    scanB_kernel<<<1, 128>>>(bsum, off, N);
    scanC_kernel<<<snb, SCAN_B>>>(off, cur, bsum, N);
    fill_kernel<<<eb, 256>>>(src, dst, cur, csr, E);

    // Layer 0 (din = 128, input raw x; also computes partial logits p)
    mma_transform<FF, 80, false><<<tb, 256>>>(x, Wn0, Ws0, bn0, fcw, t, a1, p, N);
    aggregate_kernel<<<nb64, 256>>>(off, csr, t, a1, N);

    // Layer 1 (din = 32, relu applied when reading pre-activation a1)
    mma_transform<DD, 64, true><<<tb, 256>>>(a1, Wn1, Ws1, bn1, nullptr, t, a2, p, N);
    aggregate_kernel<<<nb64, 256>>>(off, csr, t, a2, N);

    // Layer 2
    mma_transform<DD, 64, true><<<tb, 256>>>(a2, Wn2, Ws2, bn2, nullptr, t, a3, p, N);
    aggregate_kernel<<<nb64, 256>>>(off, csr, t, a3, N);

    // FC (hidden segments) + log_softmax
    fc_kernel<<<(N + 255) / 256, 256>>>(p, a1, a2, a3, fcw, fcb, out, N);
}

// round 7
// speedup vs baseline: 2.2766x; 1.0792x over previous
#include <cuda_runtime.h>
#include <cuda_fp16.h>
#include <mma.h>

using namespace nvcuda;

#define NN 100000
#define EE 3200000
#define FF 128
#define DD 32
#define SCAN_B 1024
#define SCAN_NB ((NN + SCAN_B - 1) / SCAN_B)   // 98

// Scratch (device globals: allocation-free rule)
__device__ __align__(128) __half g_t [NN * DD];    // messages, fp16
__device__ __align__(128) float  g_a1[NN * DD];    // layer outputs, PRE-relu
__device__ __align__(128) float  g_a2[NN * DD];
__device__ __align__(128) float  g_a3[NN * DD];
__device__ __align__(128) float  g_p [NN * 16];    // partial logits x@fcw_x
__device__ int g_cnt[NN];
__device__ int g_off[NN + 1];
__device__ int g_cur[NN];
__device__ __align__(16) int g_csr[EE];
__device__ int g_bsum[SCAN_NB];

// ---------------------------------------------------------------------------
// CSR build: histogram (int4 edges) -> 3-phase parallel scan -> fill
// ---------------------------------------------------------------------------
__global__ __launch_bounds__(256)
void hist_kernel(const int* __restrict__ dst, int* __restrict__ cnt, int E)
{
    const int e4 = blockIdx.x * blockDim.x + threadIdx.x;
    const int e = e4 * 4;
    if (e + 3 < E) {
        const int4 d = *(const int4*)(dst + e);
        atomicAdd(&cnt[d.x], 1);
        atomicAdd(&cnt[d.y], 1);
        atomicAdd(&cnt[d.z], 1);
        atomicAdd(&cnt[d.w], 1);
    } else {
        for (int q = e; q < E; ++q) atomicAdd(&cnt[dst[q]], 1);
    }
}

// Phase A: per-block local exclusive scan into off, block total into bsum
__global__ __launch_bounds__(SCAN_B)
void scanA_kernel(const int* __restrict__ cnt, int* __restrict__ off,
                  int* __restrict__ bsum, int n)
{
    __shared__ int warp_sums[32];
    const int tid = threadIdx.x;
    const int i = blockIdx.x * SCAN_B + tid;
    const int v = (i < n) ? cnt[i] : 0;

    int x = v;
    #pragma unroll
    for (int d = 1; d < 32; d <<= 1) {
        int y = __shfl_up_sync(0xffffffffu, x, d);
        if ((tid & 31) >= d) x += y;
    }
    if ((tid & 31) == 31) warp_sums[tid >> 5] = x;
    __syncthreads();
    if (tid < 32) {
        int w = warp_sums[tid];
        #pragma unroll
        for (int d = 1; d < 32; d <<= 1) {
            int y = __shfl_up_sync(0xffffffffu, w, d);
            if (tid >= d) w += y;
        }
        warp_sums[tid] = w;
    }
    __syncthreads();
    const int warp_off = (tid >= 32) ? warp_sums[(tid >> 5) - 1] : 0;
    const int excl = x + warp_off - v;
    if (i < n) off[i] = excl;
    if (tid == SCAN_B - 1) bsum[blockIdx.x] = excl + v;
}

// Phase B: exclusive scan of block sums
__global__ __launch_bounds__(128)
void scanB_kernel(int* __restrict__ bsum, int* __restrict__ off, int n)
{
    __shared__ int s[SCAN_NB];
    const int tid = threadIdx.x;
    if (tid < SCAN_NB) s[tid] = bsum[tid];
    __syncthreads();
    if (tid == 0) {
        int run = 0;
        #pragma unroll 4
        for (int b = 0; b < SCAN_NB; ++b) {
            int v = s[b];
            s[b] = run;
            run += v;
        }
        off[n] = run;
    }
    __syncthreads();
    if (tid < SCAN_NB) bsum[tid] = s[tid];
}

// Phase C: add block prefix, mirror into cur
__global__ __launch_bounds__(SCAN_B)
void scanC_kernel(int* __restrict__ off, int* __restrict__ cur,
                  const int* __restrict__ bsum, int n)
{
    const int i = blockIdx.x * SCAN_B + threadIdx.x;
    if (i < n) {
        const int o = off[i] + bsum[blockIdx.x];
        off[i] = o;
        cur[i] = o;
    }
}

// ---------------------------------------------------------------------------
// Transform body (wmma fp16, fp32 accumulate), called with a logical block id.
//   B = [Wn | Ws] (NCOL=64)  or  [Wn | Ws | fcw_x pad16] (NCOL=80, layer 0)
// ---------------------------------------------------------------------------
template<int DIN, int NCOL, bool RELU_IN>
__device__ __forceinline__
void transform_body(unsigned char* sraw,
                    const float* __restrict__ hin,
                    const float* __restrict__ Wn,
                    const float* __restrict__ Ws,
                    const float* __restrict__ bn,
                    const float* __restrict__ fcw,
                    __half* __restrict__ t,
                    float* __restrict__ agg,
                    float* __restrict__ p, int N, int bid)
{
    constexpr int KC    = (DIN > 64) ? 64 : DIN;
    constexpr int XS_LD = KC + 8;
    constexpr int B_LD  = NCOL + 8;
    constexpr int CS_LD = NCOL + 4;
    constexpr int NFRAG = NCOL / 16;

    __half* xs = (__half*)sraw;
    __half* bs = (__half*)(sraw + 128u * XS_LD * 2u);
    float*  cs = (float*)sraw;

    const int tid  = threadIdx.x;
    const int wid  = tid >> 5;
    const int row0 = bid * 128;

    for (int i = tid; i < DIN * 32; i += 256) {
        const int k = i / 32, j = i % 32;
        bs[k * B_LD + j]      = __float2half(Wn[i]);
        bs[k * B_LD + 32 + j] = __float2half(Ws[i]);
    }
    if (NCOL == 80) {
        for (int i = tid; i < DIN * 16; i += 256) {
            const int k = i / 16, c = i % 16;
            bs[k * B_LD + 64 + c] = (c < 10) ? __float2half(fcw[k * 10 + c])
                                             : __float2half(0.0f);
        }
    }

    wmma::fragment<wmma::accumulator, 16, 16, 16, float> c[NFRAG];
    #pragma unroll
    for (int j = 0; j < NFRAG; ++j) wmma::fill_fragment(c[j], 0.0f);

    const int m0 = wid * 16;

    for (int kc = 0; kc < DIN; kc += KC) {
        __syncthreads();
        constexpr int Q = KC / 4;
        const float4* h4 = (const float4*)hin;
        for (int i = tid; i < 128 * Q; i += 256) {
            const int r = i / Q, q = i % Q;
            const int grow = row0 + r;
            float4 v = make_float4(0.f, 0.f, 0.f, 0.f);
            if (grow < N) v = h4[grow * (DIN / 4) + kc / 4 + q];
            if (RELU_IN) {
                v.x = fmaxf(v.x, 0.f); v.y = fmaxf(v.y, 0.f);
                v.z = fmaxf(v.z, 0.f); v.w = fmaxf(v.w, 0.f);
            }
            __half2 h0 = __floats2half2_rn(v.x, v.y);
            __half2 h1 = __floats2half2_rn(v.z, v.w);
            uint2 pk;
            pk.x = *(unsigned*)&h0;
            pk.y = *(unsigned*)&h1;
            *(uint2*)(xs + r * XS_LD + q * 4) = pk;
        }
        __syncthreads();

        #pragma unroll
        for (int k0 = 0; k0 < KC; k0 += 16) {
            wmma::fragment<wmma::matrix_a, 16, 16, 16, __half, wmma::row_major> a;
            wmma::load_matrix_sync(a, xs + m0 * XS_LD + k0, XS_LD);
            #pragma unroll
            for (int j = 0; j < NFRAG; ++j) {
                wmma::fragment<wmma::matrix_b, 16, 16, 16, __half, wmma::row_major> b;
                wmma::load_matrix_sync(b, bs + (kc + k0) * B_LD + j * 16, B_LD);
                wmma::mma_sync(c[j], a, b, c[j]);
            }
        }
    }

    __syncthreads();
    #pragma unroll
    for (int j = 0; j < NFRAG; ++j)
        wmma::store_matrix_sync(cs + m0 * CS_LD + j * 16, c[j], CS_LD,
                                wmma::mem_row_major);
    __syncthreads();

    for (int i = tid; i < 128 * 16; i += 256) {
        const int r = i / 16, c2 = i % 16;
        const int node = row0 + r;
        if (node < N) {
            __half2 h = __floats2half2_rn(cs[r * CS_LD + 2 * c2],
                                          cs[r * CS_LD + 2 * c2 + 1]);
            ((__half2*)t)[node * 16 + c2] = h;
        }
    }
    for (int i = tid; i < 128 * 8; i += 256) {
        const int r = i / 8, c4 = i % 8;
        const int node = row0 + r;
        if (node < N) {
            float4 v;
            v.x = cs[r * CS_LD + 32 + c4 * 4 + 0] + bn[c4 * 4 + 0];
            v.y = cs[r * CS_LD + 32 + c4 * 4 + 1] + bn[c4 * 4 + 1];
            v.z = cs[r * CS_LD + 32 + c4 * 4 + 2] + bn[c4 * 4 + 2];
            v.w = cs[r * CS_LD + 32 + c4 * 4 + 3] + bn[c4 * 4 + 3];
            *(float4*)(agg + node * 32 + c4 * 4) = v;
        }
    }
    if (NCOL == 80) {
        for (int i = tid; i < 128 * 4; i += 256) {
            const int r = i / 4, q = i % 4;
            const int node = row0 + r;
            if (node < N) {
                float4 v;
                v.x = cs[r * CS_LD + 64 + q * 4 + 0];
                v.y = cs[r * CS_LD + 64 + q * 4 + 1];
                v.z = cs[r * CS_LD + 64 + q * 4 + 2];
                v.w = cs[r * CS_LD + 64 + q * 4 + 3];
                *(float4*)(p + node * 16 + q * 4) = v;
            }
        }
    }
}

// Shared-memory sizing for the transform instantiations
template<int DIN, int NCOL>
struct TSmem {
    static constexpr int KC    = (DIN > 64) ? 64 : DIN;
    static constexpr unsigned S_STAGE =
        128u * (KC + 8) * 2u + (unsigned)DIN * (NCOL + 8) * 2u;
    static constexpr unsigned S_EPI = 128u * (NCOL + 4) * 4u;
    static constexpr unsigned BYTES = (S_STAGE > S_EPI) ? S_STAGE : S_EPI;
};

// Standalone transform (layers 1, 2)
template<int DIN, int NCOL, bool RELU_IN>
__global__ __launch_bounds__(256)
void mma_transform(const float* __restrict__ hin,
                   const float* __restrict__ Wn,
                   const float* __restrict__ Ws,
                   const float* __restrict__ bn,
                   const float* __restrict__ fcw,
                   __half* __restrict__ t,
                   float* __restrict__ agg,
                   float* __restrict__ p, int N)
{
    __shared__ __align__(32) unsigned char sraw[TSmem<DIN, NCOL>::BYTES];
    transform_body<DIN, NCOL, RELU_IN>(sraw, hin, Wn, Ws, bn, fcw, t, agg, p,
                                       N, blockIdx.x);
}

// Fused: blocks [0,tb) = transform layer 0, blocks [tb,...) = CSR fill
__global__ __launch_bounds__(256)
void fused_t0_fill(const float* __restrict__ x,
                   const float* __restrict__ Wn,
                   const float* __restrict__ Ws,
                   const float* __restrict__ bn,
                   const float* __restrict__ fcw,
                   __half* __restrict__ t,
                   float* __restrict__ agg,
                   float* __restrict__ p, int N, int tb,
                   const int* __restrict__ src, const int* __restrict__ dst,
                   int* __restrict__ cur, int* __restrict__ csr, int E)
{
    __shared__ __align__(32) unsigned char sraw[TSmem<FF, 80>::BYTES];
    if (blockIdx.x < tb) {
        transform_body<FF, 80, false>(sraw, x, Wn, Ws, bn, fcw, t, agg, p,
                                      N, blockIdx.x);
    } else {
        const int e4 = (blockIdx.x - tb) * blockDim.x + threadIdx.x;
        const int e = e4 * 4;
        if (e + 3 < E) {
            const int4 s = *(const int4*)(src + e);
            const int4 d = *(const int4*)(dst + e);
            csr[atomicAdd(&cur[d.x], 1)] = s.x;
            csr[atomicAdd(&cur[d.y], 1)] = s.y;
            csr[atomicAdd(&cur[d.z], 1)] = s.z;
            csr[atomicAdd(&cur[d.w], 1)] = s.w;
        } else {
            for (int q = e; q < E; ++q)
                csr[atomicAdd(&cur[dst[q]], 1)] = src[q];
        }
    }
}

// ---------------------------------------------------------------------------
// CSR aggregate: agg[n] += sum_{e in in(n)} t[csr_src[e]]
// 4 threads per node (16B of columns each). Indices loaded as int4 shared by
// the 4 lanes (merged wavefront), 8 edges per main-loop iteration.
// ---------------------------------------------------------------------------
__global__ __launch_bounds__(256)
void aggregate_kernel(const int* __restrict__ off, const int* __restrict__ csr,
                      const __half* __restrict__ t, float* __restrict__ agg,
                      int N)
{
    const int tid  = threadIdx.x;
    const int node = blockIdx.x * 64 + (tid >> 2);
    if (node >= N) return;
    const int lane = tid & 3;

    const int beg = off[node];
    const int end = off[node + 1];

    const uint4* tp = (const uint4*)t;   // 4 x uint4 per 32-half row

    float a0 = 0.f, a1 = 0.f, a2 = 0.f, a3 = 0.f;
    float a4 = 0.f, a5 = 0.f, a6 = 0.f, a7 = 0.f;

    #define ACC(v) do {                                             \
        const float2 f0 = __half22float2(*(const __half2*)&(v).x);  \
        const float2 f1 = __half22float2(*(const __half2*)&(v).y);  \
        const float2 f2 = __half22float2(*(const __half2*)&(v).z);  \
        const float2 f3 = __half22float2(*(const __half2*)&(v).w);  \
        a0 += f0.x; a1 += f0.y; a2 += f1.x; a3 += f1.y;             \
        a4 += f2.x; a5 += f2.y; a6 += f3.x; a7 += f3.y; } while (0)

    int j = beg;
    const int jal = (beg + 3) & ~3;      // first 16B-aligned csr index
    // head peel (scalar)
    for (; j < end && j < jal; ++j) {
        const uint4 v = tp[csr[j] * 4 + lane];
        ACC(v);
    }
    // 8-edge vector loop: 2 int4 index loads (same addr across 4 lanes)
    for (; j + 8 <= end; j += 8) {
        const int4 i0 = *(const int4*)(csr + j);
        const int4 i1 = *(const int4*)(csr + j + 4);
        const uint4 v0 = tp[i0.x * 4 + lane];
        const uint4 v1 = tp[i0.y * 4 + lane];
        const uint4 v2 = tp[i0.z * 4 + lane];
        const uint4 v3 = tp[i0.w * 4 + lane];
        const uint4 v4 = tp[i1.x * 4 + lane];
        const uint4 v5 = tp[i1.y * 4 + lane];
        const uint4 v6 = tp[i1.z * 4 + lane];
        const uint4 v7 = tp[i1.w * 4 + lane];
        ACC(v0); ACC(v1); ACC(v2); ACC(v3);
        ACC(v4); ACC(v5); ACC(v6); ACC(v7);
    }
    // 4-edge step
    for (; j + 4 <= end; j += 4) {
        const int4 i0 = *(const int4*)(csr + j);
        const uint4 v0 = tp[i0.x * 4 + lane];
        const uint4 v1 = tp[i0.y * 4 + lane];
        const uint4 v2 = tp[i0.z * 4 + lane];
        const uint4 v3 = tp[i0.w * 4 + lane];
        ACC(v0); ACC(v1); ACC(v2); ACC(v3);
    }
    // tail
    for (; j < end; ++j) {
        const uint4 v = tp[csr[j] * 4 + lane];
        ACC(v);
    }
    #undef ACC

    float4* ap = (float4*)(agg + node * 32 + lane * 8);
    float4 s0 = ap[0], s1 = ap[1];
    s0.x += a0; s0.y += a1; s0.z += a2; s0.w += a3;
    s1.x += a4; s1.y += a5; s1.z += a6; s1.w += a7;
    ap[0] = s0; ap[1] = s1;
}

// ---------------------------------------------------------------------------
// Final FC (hidden segments only; x segment pre-fused into p) + log_softmax
// ---------------------------------------------------------------------------
__global__ __launch_bounds__(256)
void fc_kernel(const float* __restrict__ p,
               const float* __restrict__ a1, const float* __restrict__ a2,
               const float* __restrict__ a3,
               const float* __restrict__ fcw, const float* __restrict__ fcb,
               float* __restrict__ out, int N)
{
    __shared__ float w_s[3 * DD * 10];
    __shared__ float b_s[10];
    for (int i = threadIdx.x; i < 3 * DD * 10; i += blockDim.x)
        w_s[i] = fcw[FF * 10 + i];
    if (threadIdx.x < 10) b_s[threadIdx.x] = fcb[threadIdx.x];
    __syncthreads();

    const int node = blockIdx.x * blockDim.x + threadIdx.x;
    if (node >= N) return;

    float acc[10];
    {
        const float4* pr = (const float4*)(p + node * 16);
        const float4 p0 = pr[0], p1 = pr[1];
        const float2 p2 = *(const float2*)(p + node * 16 + 8);
        acc[0] = p0.x + b_s[0]; acc[1] = p0.y + b_s[1];
        acc[2] = p0.z + b_s[2]; acc[3] = p0.w + b_s[3];
        acc[4] = p1.x + b_s[4]; acc[5] = p1.y + b_s[5];
        acc[6] = p1.z + b_s[6]; acc[7] = p1.w + b_s[7];
        acc[8] = p2.x + b_s[8]; acc[9] = p2.y + b_s[9];
    }

    const float* const hs[3] = {a1, a2, a3};
    int k = 0;
    #pragma unroll
    for (int l = 0; l < 3; ++l) {
        const float4* r = (const float4*)(hs[l] + node * DD);
        #pragma unroll
        for (int q = 0; q < DD / 4; ++q) {
            float4 f4 = r[q];
            float fv[4] = {f4.x, f4.y, f4.z, f4.w};
            #pragma unroll
            for (int j = 0; j < 4; ++j) {
                const float f = fmaxf(fv[j], 0.0f);
                #pragma unroll
                for (int c = 0; c < 10; ++c)
                    acc[c] = fmaf(f, w_s[k * 10 + c], acc[c]);
                ++k;
            }
        }
    }

    float m = acc[0];
    #pragma unroll
    for (int c = 1; c < 10; ++c) m = fmaxf(m, acc[c]);
    float s = 0.f;
    #pragma unroll
    for (int c = 0; c < 10; ++c) s += expf(acc[c] - m);
    const float lse = m + logf(s);
    #pragma unroll
    for (int c = 0; c < 10; ++c) out[node * 10 + c] = acc[c] - lse;
}

// ---------------------------------------------------------------------------
extern "C" void kernel_launch(void* const* d_in, const int* in_sizes, int n_in,
                              void* d_out, int out_size)
{
    const float* x   = (const float*)d_in[0];
    const int*   src = (const int*)  d_in[1];
    const int*   dst = (const int*)  d_in[2];
    const float* Wn0 = (const float*)d_in[3];
    const float* bn0 = (const float*)d_in[4];
    const float* Ws0 = (const float*)d_in[5];
    const float* Wn1 = (const float*)d_in[6];
    const float* bn1 = (const float*)d_in[7];
    const float* Ws1 = (const float*)d_in[8];
    const float* Wn2 = (const float*)d_in[9];
    const float* bn2 = (const float*)d_in[10];
    const float* Ws2 = (const float*)d_in[11];
    const float* fcw = (const float*)d_in[12];
    const float* fcb = (const float*)d_in[13];
    float* out = (float*)d_out;

    const int N = in_sizes[0] / FF;
    const int E = in_sizes[1];

    __half* t;
    float *a1, *a2, *a3, *p;
    int *cnt, *off, *cur, *csr, *bsum;
    cudaGetSymbolAddress((void**)&t,    g_t);
    cudaGetSymbolAddress((void**)&a1,   g_a1);
    cudaGetSymbolAddress((void**)&a2,   g_a2);
    cudaGetSymbolAddress((void**)&a3,   g_a3);
    cudaGetSymbolAddress((void**)&p,    g_p);
    cudaGetSymbolAddress((void**)&cnt,  g_cnt);
    cudaGetSymbolAddress((void**)&off,  g_off);
    cudaGetSymbolAddress((void**)&cur,  g_cur);
    cudaGetSymbolAddress((void**)&csr,  g_csr);
    cudaGetSymbolAddress((void**)&bsum, g_bsum);

    const int e4b  = ((E + 3) / 4 + 255) / 256;
    const int nb64 = (N + 63) / 64;
    const int tb   = (N + 127) / 128;
    const int snb  = (N + SCAN_B - 1) / SCAN_B;

    // CSR build prefix (hist + scans)
    cudaMemsetAsync(cnt, 0, N * sizeof(int));
    hist_kernel<<<e4b, 256>>>(dst, cnt, E);
    scanA_kernel<<<snb, SCAN_B>>>(cnt, off, bsum, N);
    scanB_kernel<<<1, 128>>>(bsum, off, N);
    scanC_kernel<<<snb, SCAN_B>>>(off, cur, bsum, N);

    // Fused: transform layer 0 (tb blocks) || CSR fill (e4b blocks)
    fused_t0_fill<<<tb + e4b, 256>>>(x, Wn0, Ws0, bn0, fcw, t, a1, p, N, tb,
                                     src, dst, cur, csr, E);
    aggregate_kernel<<<nb64, 256>>>(off, csr, t, a1, N);

    // Layer 1 (din = 32, relu applied when reading pre-activation a1)
    mma_transform<DD, 64, true><<<tb, 256>>>(a1, Wn1, Ws1, bn1, nullptr, t, a2, p, N);
    aggregate_kernel<<<nb64, 256>>>(off, csr, t, a2, N);

    // Layer 2
    mma_transform<DD, 64, true><<<tb, 256>>>(a2, Wn2, Ws2, bn2, nullptr, t, a3, p, N);
    aggregate_kernel<<<nb64, 256>>>(off, csr, t, a3, N);

    // FC (hidden segments) + log_softmax
    fc_kernel<<<(N + 255) / 256, 256>>>(p, a1, a2, a3, fcw, fcb, out, N);
}